// round 15
// baseline (speedup 1.0000x reference)
#include <cuda_runtime.h>
#include <cuda_bf16.h>
#include <cstdint>

// GMMVAE ELBO, warp-specialized + rebalanced: warps 8-15 do the mixture stage
// then join the mean-GEMM tail. Static partitions -> deterministic.
typedef unsigned long long ull;

#define B_TOT 16384
#define XD 784
#define ZD 64
#define KK 64
#define ROWS 128
#define THREADS 512
#define NBLK (B_TOT / ROWS)   // 128
#define RSTR 66
#define LOG2PI 1.8378770664093453
#define FIXSCALE 262144.0

__device__ float g_s2T[ZD * KK];
__device__ float g_na2T[ZD * KK];
__device__ float g_cc2[KK];
__device__ float g_ck2[KK];
__device__ ull g_acc;
__device__ unsigned g_cnt;
__device__ __align__(16) __nv_bfloat16 g_Wt[XD * 64];  // [c][z] 128B swizzled rows

// ---- smem byte offsets ----
#define OFF_RED   0        // 32 floats
#define OFF_QSUM  128      // -> 640
#define OFF_BIAS  640      // -> 3776
#define OFF_ZBF   3840     // 16384 -> 20224
#define OFF_WT    20224    // 50 tiles * 1024 = 51200 -> 71424
#define OFF_ZR    71424    // 33792 -> 105216
#define OFF_V1    105216   // -> 139008
#define OFF_QM    139008   // -> 172800
#define OFF_S2T   172800   // -> 189184
#define OFF_NA2T  189184   // -> 205568
#define SMEM_BYTES 205568

__device__ __forceinline__ uint32_t smem_u32(const void* p) {
    uint32_t a;
    asm("{ .reg .u64 t; cvta.to.shared.u64 t, %1; cvt.u32.u64 %0, t; }" : "=r"(a) : "l"(p));
    return a;
}
__device__ __forceinline__ ull fma2o(ull a, ull b, ull c) {
    ull d;
    asm("fma.rn.f32x2 %0, %1, %2, %3;" : "=l"(d) : "l"(a), "l"(b), "l"(c));
    return d;
}
__device__ __forceinline__ ull dup2(float x) {
    ull r;
    asm("mov.b64 %0, {%1, %1};" : "=l"(r) : "f"(x));
    return r;
}
__device__ __forceinline__ void unpack2(ull v, float& lo, float& hi) {
    asm("mov.b64 {%0, %1}, %2;" : "=f"(lo), "=f"(hi) : "l"(v));
}
__device__ __forceinline__ void ldm_x4(uint32_t& r0, uint32_t& r1, uint32_t& r2,
                                       uint32_t& r3, uint32_t addr) {
    asm volatile("ldmatrix.sync.aligned.m8n8.x4.shared.b16 {%0,%1,%2,%3}, [%4];"
                 : "=r"(r0), "=r"(r1), "=r"(r2), "=r"(r3) : "r"(addr));
}
__device__ __forceinline__ void mma_bf16(float& c0, float& c1, float& c2, float& c3,
                                         uint32_t a0, uint32_t a1, uint32_t a2, uint32_t a3,
                                         uint32_t b0, uint32_t b1) {
    asm volatile("mma.sync.aligned.m16n8k16.row.col.f32.bf16.bf16.f32 "
                 "{%0,%1,%2,%3}, {%4,%5,%6,%7}, {%8,%9}, {%0,%1,%2,%3};"
                 : "+f"(c0), "+f"(c1), "+f"(c2), "+f"(c3)
                 : "r"(a0), "r"(a1), "r"(a2), "r"(a3), "r"(b0), "r"(b1));
}
__device__ __forceinline__ uint32_t swz(int r, int zp) {
    return (uint32_t)(r * 128 + (((zp >> 2) ^ (r & 7)) << 4) + 4 * (zp & 3));
}

// ======================= prep kernel (grid 15) =======================
__global__ void prep_kernel(const float* __restrict__ W,
                            const float* __restrict__ pmu,
                            const float* __restrict__ pls) {
    const int b = blockIdx.x, tid = threadIdx.x;
    if (b < 14) {
        __shared__ float sc[64 * 57];
        const int c0 = b * 56;
        for (int i = tid; i < 64 * 56; i += 256) {
            const int z = i / 56, c = i - z * 56;
            sc[z * 57 + c] = W[z * XD + c0 + c];
        }
        __syncthreads();
        for (int i = tid; i < 56 * 32; i += 256) {
            const int c = i >> 5, zp = i & 31;
            __nv_bfloat162 bv = __floats2bfloat162_rn(sc[(2 * zp) * 57 + c],
                                                      sc[(2 * zp + 1) * 57 + c]);
            *(uint32_t*)((char*)g_Wt + swz(c0 + c, zp)) = *(uint32_t*)&bv;
        }
    } else {
        const int k = tid >> 2, q = tid & 3;
        float lsum = 0.f, c1 = 0.f;
#pragma unroll
        for (int i = 0; i < 16; i++) {
            const int z = 16 * q + i;
            float ls = pls[k * ZD + z];
            float mu = pmu[k * ZD + z];
            float s2i = expf(-2.f * ls);
            g_s2T[z * KK + k] = s2i;
            g_na2T[z * KK + k] = -2.f * mu * s2i;
            lsum += ls;
            c1 = fmaf(mu * mu, s2i, c1);
        }
#pragma unroll
        for (int o = 1; o < 4; o <<= 1) {
            lsum += __shfl_xor_sync(~0u, lsum, o);
            c1 += __shfl_xor_sync(~0u, c1, o);
        }
        if (q == 0) {
            g_cc2[k] = (float)(-(double)lsum - 32.0 * LOG2PI - 0.5 * (double)c1);
            g_ck2[k] = lsum + 0.5f * c1;
        }
        if (tid == 0) { g_acc = 0ull; g_cnt = 0u; }
    }
}

// ======================= main kernel =======================
extern __shared__ char smem[];

#define TILE_BODY(bf, xa, xb, bb) do {                                         \
    float cA0 = 0.f, cA1 = 0.f, cA2 = 0.f, cA3 = 0.f;                          \
    float cB0 = 0.f, cB1 = 0.f, cB2 = 0.f, cB3 = 0.f;                          \
    mma_bf16(cA0, cA1, cA2, cA3, a[0], a[1], a[2], a[3], (bf)[0], (bf)[1]);    \
    mma_bf16(cB0, cB1, cB2, cB3, a[8], a[9], a[10], a[11], (bf)[4], (bf)[5]);  \
    mma_bf16(cA0, cA1, cA2, cA3, a[4], a[5], a[6], a[7], (bf)[2], (bf)[3]);    \
    mma_bf16(cB0, cB1, cB2, cB3, a[12], a[13], a[14], a[15], (bf)[6], (bf)[7]);\
    float d_;                                                                  \
    d_ = ((xa).x - (bb).x) - (cA0 + cB0); px = fmaf(d_, d_, px);               \
    d_ = ((xa).y - (bb).y) - (cA1 + cB1); px = fmaf(d_, d_, px);               \
    d_ = ((xb).x - (bb).x) - (cA2 + cB2); px = fmaf(d_, d_, px);               \
    d_ = ((xb).y - (bb).y) - (cA3 + cB3); px = fmaf(d_, d_, px);               \
} while (0)

// GEMM over global tiles [glo, ghi), (ghi-glo) EVEN. Buffer origin = tile tbase.
__device__ __forceinline__ void gemm_range(
    float& px, const uint32_t* a, uint32_t wb0, uint32_t wb1, int tbase,
    int glo, int ghi, const float* pxA, const float* pxB,
    const float* biasS, int fcol)
{
    uint32_t b0[8], b1[8];
    float2 xaA, xbA, bbA, xaB, xbB, bbB;
    const int n = ghi - glo;
#define LDBR(dst, gt) do {                                                     \
    const uint32_t o_ = (uint32_t)((gt) - tbase) * 1024u;                      \
    ldm_x4((dst)[0], (dst)[1], (dst)[2], (dst)[3], wb0 + o_);                  \
    ldm_x4((dst)[4], (dst)[5], (dst)[6], (dst)[7], wb1 + o_);                  \
} while (0)
#define LDXR(xa, xb, bb, gt) do {                                              \
    const int c_ = 8 * (gt);                                                   \
    bb = *(const float2*)(biasS + c_ + fcol);                                  \
    xa = *(const float2*)(pxA + c_);                                           \
    xb = *(const float2*)(pxB + c_);                                           \
} while (0)
    LDBR(b0, glo);
    LDXR(xaA, xbA, bbA, glo);
    for (int i = 0; i < n; i += 2) {
        LDBR(b1, glo + i + 1);
        LDXR(xaB, xbB, bbB, glo + i + 1);
        TILE_BODY(b0, xaA, xbA, bbA);
        if (i + 2 < n) {
            LDBR(b0, glo + i + 2);
            LDXR(xaA, xbA, bbA, glo + i + 2);
        }
        TILE_BODY(b1, xaB, xbB, bbB);
    }
#undef LDBR
#undef LDXR
}

#define LOAD_AFRAGS() do {                                                     \
    const int ra_ = mrow + lr + 8 * (g & 1);                                   \
    const uint32_t ab_ = sbase + OFF_ZBF + ra_ * 128;                          \
    _Pragma("unroll")                                                          \
    for (int kt_ = 0; kt_ < 4; kt_++)                                          \
        ldm_x4(a[4 * kt_], a[4 * kt_ + 1], a[4 * kt_ + 2], a[4 * kt_ + 3],     \
               ab_ + (uint32_t)(((gx + 2 * kt_) ^ (ra_ & 7)) << 4));           \
} while (0)

__global__ __launch_bounds__(THREADS, 1)
void main_kernel(const float* __restrict__ x, const float* __restrict__ pi,
                 const float* __restrict__ qmu, const float* __restrict__ qls,
                 const float* __restrict__ eps, const float* __restrict__ bdec,
                 float* __restrict__ out) {
    const int tid = threadIdx.x;
    const int wid = tid >> 5, lane = tid & 31;
    const int rowbase = blockIdx.x * ROWS;
    const uint32_t sbase = smem_u32(smem);
    float* red = (float*)(smem + OFF_RED);
    float* qsumS = (float*)(smem + OFF_QSUM);
    float* biasS = (float*)(smem + OFF_BIAS);
    float* zR = (float*)(smem + OFF_ZR);
    float* v1S = (float*)(smem + OFF_V1);
    float* qmS = (float*)(smem + OFF_QM);
    float* s2T = (float*)(smem + OFF_S2T);
    float* na2T = (float*)(smem + OFF_NA2T);

    // ---- init: W buffer A (tiles 0-49), tables, bias, z/v1/qm/qsum ----
    {
        const uint4* src = (const uint4*)g_Wt;
        uint4* dst = (uint4*)(smem + OFF_WT);
        for (int i = tid; i < 3200; i += THREADS) dst[i] = src[i];
        const uint4* s1 = (const uint4*)g_s2T;
        const uint4* s2 = (const uint4*)g_na2T;
        uint4* d1 = (uint4*)s2T;
        uint4* d2 = (uint4*)na2T;
        for (int i = tid; i < (ZD * KK) / 4; i += THREADS) {
            d1[i] = s1[i];
            d2[i] = s2[i];
        }
    }
    for (int i = tid; i < XD; i += THREADS) biasS[i] = bdec[i];
#pragma unroll
    for (int k = 0; k < 8; k++) {
        const int i = tid + THREADS * k;
        const int r = i >> 5, zp = i & 31;
        const int gi = (rowbase + r) * ZD + 2 * zp;
        float2 qm2 = *(const float2*)(qmu + gi);
        float2 ql2 = *(const float2*)(qls + gi);
        float2 ep2 = *(const float2*)(eps + gi);
        float qs0 = expf(ql2.x), qs1 = expf(ql2.y);
        float z0 = fmaf(qs0, ep2.x, qm2.x);
        float z1 = fmaf(qs1, ep2.y, qm2.y);
        __nv_bfloat162 bv = __floats2bfloat162_rn(z0, z1);
        *(uint32_t*)(smem + OFF_ZBF + swz(r, zp)) = *(uint32_t*)&bv;
        const int rb = r * RSTR + 2 * zp;
        *(float2*)(zR + rb) = make_float2(z0, z1);
        *(float2*)(v1S + rb) = make_float2(fmaf(qs0, qs0, qm2.x * qm2.x),
                                           fmaf(qs1, qs1, qm2.y * qm2.y));
        *(float2*)(qmS + rb) = qm2;
        float qs = ql2.x + ql2.y;
#pragma unroll
        for (int o = 16; o; o >>= 1) qs += __shfl_xor_sync(~0u, qs, o);
        if (lane == 0) qsumS[r] = qs;
    }
    __syncthreads();

    // ---- common GEMM lane geometry (strip = wid & 7) ----
    const int strip = wid & 7;
    const int g = lane >> 3, lr = lane & 7, gx = g >> 1;
    const int mrow = 16 * strip;
    const int fcol = 2 * (lane & 3);
    const uint32_t wb0 = sbase + OFF_WT + lr * 128 + (uint32_t)((g ^ lr) << 4);
    const uint32_t wb1 = sbase + OFF_WT + lr * 128 + (uint32_t)(((g + 4) ^ lr) << 4);
    const float* pxA = x + (size_t)(rowbase + mrow + (lane >> 2)) * XD + fcol;
    const float* pxB = pxA + 8 * XD;
    float px = 0.f;
    uint32_t a[16];

    if (wid < 8) {
        // ======== Phase 1, stage-1 warps: tiles [0,42) ========
        LOAD_AFRAGS();
        gemm_range(px, a, wb0, wb1, 0, 0, 42, pxA, pxB, biasS, fcol);
    } else {
        // ======== Phase 1, stage-2 warps: mixture, then tiles [42,50) ========
        const int st = tid - 256;
        const int tx = st & 7, ty = st >> 3;
        const int kb = 8 * tx;
        const float* s2p = s2T + kb;
        const float* nap = na2T + kb;
        float cc[8], ck[8];
        *(float4*)cc = *(const float4*)(g_cc2 + kb);
        *(float4*)(cc + 4) = *(const float4*)(g_cc2 + kb + 4);
        *(float4*)ck = *(const float4*)(g_ck2 + kb);
        *(float4*)(ck + 4) = *(const float4*)(g_ck2 + kb + 4);
        float kl_acc = 0.f;

#pragma unroll 1
        for (int pass = 0; pass < 2; pass++) {
            const int r0 = 2 * ty + 64 * pass;
            ull accC[2][4], accK[2][4];
#pragma unroll
            for (int r = 0; r < 2; r++)
#pragma unroll
                for (int k = 0; k < 4; k++) { accC[r][k] = 0ull; accK[r][k] = 0ull; }
            const int rb0 = r0 * RSTR, rb1 = rb0 + RSTR;
#pragma unroll 2
            for (int z = 0; z < ZD; z += 2) {
                ulonglong2 sA0 = *(const ulonglong2*)(s2p + z * KK);
                ulonglong2 sB0 = *(const ulonglong2*)(s2p + z * KK + 4);
                ulonglong2 nA0 = *(const ulonglong2*)(nap + z * KK);
                ulonglong2 nB0 = *(const ulonglong2*)(nap + z * KK + 4);
                ulonglong2 sA1 = *(const ulonglong2*)(s2p + (z + 1) * KK);
                ulonglong2 sB1 = *(const ulonglong2*)(s2p + (z + 1) * KK + 4);
                ulonglong2 nA1 = *(const ulonglong2*)(nap + (z + 1) * KK);
                ulonglong2 nB1 = *(const ulonglong2*)(nap + (z + 1) * KK + 4);
#pragma unroll
                for (int r = 0; r < 2; r++) {
                    const int rb = (r ? rb1 : rb0) + z;
                    float2 zf = *(const float2*)(zR + rb);
                    float2 vf = *(const float2*)(v1S + rb);
                    float2 qf = *(const float2*)(qmS + rb);
                    ull zd = dup2(zf.x), vd = dup2(vf.x), qd = dup2(qf.x);
                    ull t;
                    t = fma2o(sA0.x, zd, nA0.x); accC[r][0] = fma2o(t, zd, accC[r][0]);
                    t = fma2o(sA0.y, zd, nA0.y); accC[r][1] = fma2o(t, zd, accC[r][1]);
                    t = fma2o(sB0.x, zd, nB0.x); accC[r][2] = fma2o(t, zd, accC[r][2]);
                    t = fma2o(sB0.y, zd, nB0.y); accC[r][3] = fma2o(t, zd, accC[r][3]);
                    accK[r][0] = fma2o(sA0.x, vd, accK[r][0]);
                    accK[r][0] = fma2o(nA0.x, qd, accK[r][0]);
                    accK[r][1] = fma2o(sA0.y, vd, accK[r][1]);
                    accK[r][1] = fma2o(nA0.y, qd, accK[r][1]);
                    accK[r][2] = fma2o(sB0.x, vd, accK[r][2]);
                    accK[r][2] = fma2o(nB0.x, qd, accK[r][2]);
                    accK[r][3] = fma2o(sB0.y, vd, accK[r][3]);
                    accK[r][3] = fma2o(nB0.y, qd, accK[r][3]);
                    zd = dup2(zf.y); vd = dup2(vf.y); qd = dup2(qf.y);
                    t = fma2o(sA1.x, zd, nA1.x); accC[r][0] = fma2o(t, zd, accC[r][0]);
                    t = fma2o(sA1.y, zd, nA1.y); accC[r][1] = fma2o(t, zd, accC[r][1]);
                    t = fma2o(sB1.x, zd, nB1.x); accC[r][2] = fma2o(t, zd, accC[r][2]);
                    t = fma2o(sB1.y, zd, nB1.y); accC[r][3] = fma2o(t, zd, accC[r][3]);
                    accK[r][0] = fma2o(sA1.x, vd, accK[r][0]);
                    accK[r][0] = fma2o(nA1.x, qd, accK[r][0]);
                    accK[r][1] = fma2o(sA1.y, vd, accK[r][1]);
                    accK[r][1] = fma2o(nA1.y, qd, accK[r][1]);
                    accK[r][2] = fma2o(sB1.x, vd, accK[r][2]);
                    accK[r][2] = fma2o(nB1.x, qd, accK[r][2]);
                    accK[r][3] = fma2o(sB1.y, vd, accK[r][3]);
                    accK[r][3] = fma2o(nB1.y, qd, accK[r][3]);
                }
            }
            // ---- fused softmax/KL within the 8-lane group ----
#pragma unroll
            for (int r = 0; r < 2; r++) {
                float comp[8], klz[8];
#pragma unroll
                for (int q = 0; q < 4; q++) {
                    float lo, hi;
                    unpack2(accC[r][q], lo, hi);
                    comp[2 * q] = fmaf(-0.5f, lo, cc[2 * q]);
                    comp[2 * q + 1] = fmaf(-0.5f, hi, cc[2 * q + 1]);
                    unpack2(accK[r][q], lo, hi);
                    klz[2 * q] = fmaf(0.5f, lo, ck[2 * q]);
                    klz[2 * q + 1] = fmaf(0.5f, hi, ck[2 * q + 1]);
                }
                const int rl = r0 + r;
                const float* pip = pi + (size_t)(rowbase + rl) * KK + kb;
                float4 pa = *(const float4*)pip;
                float4 pb = *(const float4*)(pip + 4);
                float lp[8];
                lp[0] = __logf(pa.x); lp[1] = __logf(pa.y);
                lp[2] = __logf(pa.z); lp[3] = __logf(pa.w);
                lp[4] = __logf(pb.x); lp[5] = __logf(pb.y);
                lp[6] = __logf(pb.z); lp[7] = __logf(pb.w);
                float p[8], m = -1e30f;
#pragma unroll
                for (int j = 0; j < 8; j++) { p[j] = comp[j] + lp[j]; m = fmaxf(m, p[j]); }
#pragma unroll
                for (int o = 1; o < 8; o <<= 1) m = fmaxf(m, __shfl_xor_sync(~0u, m, o));
                float e[8], es = 0.f;
#pragma unroll
                for (int j = 0; j < 8; j++) { e[j] = __expf(p[j] - m); es += e[j]; }
#pragma unroll
                for (int o = 1; o < 8; o <<= 1) es += __shfl_xor_sync(~0u, es, o);
                const float lse = m + __logf(es);
                const float inv = 1.f / es;
                const float klf = qsumS[rl] + 32.f + lse;
                float ctr = 0.f;
#pragma unroll
                for (int j = 0; j < 8; j++)
                    ctr = fmaf(e[j], (comp[j] - lse) + (klz[j] - klf + lse), ctr);
                ctr *= inv;
#pragma unroll
                for (int o = 1; o < 8; o <<= 1) ctr += __shfl_xor_sync(~0u, ctr, o);
                kl_acc += ctr;
            }
        }
        kl_acc += __shfl_xor_sync(~0u, kl_acc, 8);
        kl_acc += __shfl_xor_sync(~0u, kl_acc, 16);
        if (lane == 0) red[16 + wid] = kl_acc;

        // join the GEMM: tiles [42,50) of strip wid-8
        LOAD_AFRAGS();
        gemm_range(px, a, wb0, wb1, 0, 42, 50, pxA, pxB, biasS, fcol);
    }

    // ======== Phase 2: reload W (tiles 50-97), all 16 warps split 24/24 ======
    __syncthreads();
    {
        const uint4* src = (const uint4*)((const char*)g_Wt + 51200);
        uint4* dst = (uint4*)(smem + OFF_WT);
        for (int i = tid; i < 3072; i += THREADS) dst[i] = src[i];
    }
    __syncthreads();
    {
        const int sub = wid >> 3;
        gemm_range(px, a, wb0, wb1, 50, 50 + 24 * sub, 74 + 24 * sub,
                   pxA, pxB, biasS, fcol);
    }

    // ---- px reduce (all 16 warps) + join + grid reduction ----
#pragma unroll
    for (int o = 16; o; o >>= 1) px += __shfl_xor_sync(~0u, px, o);
    if (lane == 0) red[wid] = px;
    __syncthreads();
    if (tid == 0) {
        float sp = 0.f, sk = 0.f;
#pragma unroll
        for (int w = 0; w < 16; w++) sp += red[w];
#pragma unroll
        for (int w = 24; w < 32; w++) sk += red[w];
        const double part = -0.5 * (double)sp - (double)sk;
        const long long q = llrint(part * FIXSCALE);
        atomicAdd(&g_acc, (ull)q);
        __threadfence();
        const unsigned t = atomicAdd(&g_cnt, 1u);
        if (t == NBLK - 1) {
            const long long tot = (long long)atomicAdd(&g_acc, 0ull);
            out[0] = (float)((double)tot / FIXSCALE / 16384.0
                             - 0.5 * LOG2PI * (double)XD);
            g_cnt = 0u;
            g_acc = 0ull;
        }
    }
}

extern "C" void kernel_launch(void* const* d_in, const int* in_sizes, int n_in,
                              void* d_out, int out_size) {
    (void)in_sizes; (void)n_in; (void)out_size;
    const float* x    = (const float*)d_in[0];
    const float* pi   = (const float*)d_in[1];
    const float* qmu  = (const float*)d_in[2];
    const float* qls  = (const float*)d_in[3];
    const float* eps  = (const float*)d_in[4];
    const float* pmu  = (const float*)d_in[5];
    const float* pls  = (const float*)d_in[6];
    const float* W    = (const float*)d_in[7];
    const float* bdec = (const float*)d_in[8];

    cudaFuncSetAttribute(main_kernel, cudaFuncAttributeMaxDynamicSharedMemorySize,
                         SMEM_BYTES);
    prep_kernel<<<15, 256>>>(W, pmu, pls);
    main_kernel<<<NBLK, THREADS, SMEM_BYTES>>>(x, pi, qmu, qls, eps, bdec,
                                               (float*)d_out);
}

// round 16
// speedup vs baseline: 1.1008x; 1.1008x over previous
#include <cuda_runtime.h>
#include <cuda_bf16.h>
#include <cstdint>

// GMMVAE ELBO, warp-specialized (R13) + per-warp cp.async x pipeline (depth 8).
// Warps 0-7: mean GEMM + log_px. Warps 8-15: mixture + in-register softmax/KL.
typedef unsigned long long ull;

#define B_TOT 16384
#define XD 784
#define ZD 64
#define KK 64
#define ROWS 128
#define THREADS 512
#define NBLK (B_TOT / ROWS)   // 128
#define RSTR 66
#define LOG2PI 1.8378770664093453
#define FIXSCALE 262144.0

__device__ float g_s2T[ZD * KK];
__device__ float g_na2T[ZD * KK];
__device__ float g_cc2[KK];
__device__ float g_ck2[KK];
__device__ ull g_acc;
__device__ unsigned g_cnt;
__device__ __align__(16) __nv_bfloat16 g_Wt[XD * 64];  // [c][z] 128B swizzled rows

// ---- smem byte offsets ----
#define OFF_RED   0        // 128
#define OFF_QSUM  128      // -> 640
#define OFF_BIAS  640      // -> 3776 (pad to 3840)
#define OFF_ZBF   3840     // 16384 -> 20224
#define OFF_XP    20224    // 8 warps * 8 slots * 512B = 32768 -> 52992
#define OFF_WT    52992    // 40 tiles * 1024 = 40960 -> 93952
#define OFF_ZR    93952    // 33792 -> 127744
#define OFF_V1    127744   // -> 161536
#define OFF_QM    161536   // -> 195328
#define OFF_S2T   195328   // -> 211712
#define OFF_NA2T  211712   // -> 228096
#define SMEM_BYTES 228096

__device__ __forceinline__ uint32_t smem_u32(const void* p) {
    uint32_t a;
    asm("{ .reg .u64 t; cvta.to.shared.u64 t, %1; cvt.u32.u64 %0, t; }" : "=r"(a) : "l"(p));
    return a;
}
__device__ __forceinline__ ull fma2o(ull a, ull b, ull c) {
    ull d;
    asm("fma.rn.f32x2 %0, %1, %2, %3;" : "=l"(d) : "l"(a), "l"(b), "l"(c));
    return d;
}
__device__ __forceinline__ ull dup2(float x) {
    ull r;
    asm("mov.b64 %0, {%1, %1};" : "=l"(r) : "f"(x));
    return r;
}
__device__ __forceinline__ void unpack2(ull v, float& lo, float& hi) {
    asm("mov.b64 {%0, %1}, %2;" : "=f"(lo), "=f"(hi) : "l"(v));
}
__device__ __forceinline__ void ldm_x4(uint32_t& r0, uint32_t& r1, uint32_t& r2,
                                       uint32_t& r3, uint32_t addr) {
    asm volatile("ldmatrix.sync.aligned.m8n8.x4.shared.b16 {%0,%1,%2,%3}, [%4];"
                 : "=r"(r0), "=r"(r1), "=r"(r2), "=r"(r3) : "r"(addr));
}
__device__ __forceinline__ void mma_bf16(float& c0, float& c1, float& c2, float& c3,
                                         uint32_t a0, uint32_t a1, uint32_t a2, uint32_t a3,
                                         uint32_t b0, uint32_t b1) {
    asm volatile("mma.sync.aligned.m16n8k16.row.col.f32.bf16.bf16.f32 "
                 "{%0,%1,%2,%3}, {%4,%5,%6,%7}, {%8,%9}, {%0,%1,%2,%3};"
                 : "+f"(c0), "+f"(c1), "+f"(c2), "+f"(c3)
                 : "r"(a0), "r"(a1), "r"(a2), "r"(a3), "r"(b0), "r"(b1));
}
__device__ __forceinline__ uint32_t swz(int r, int zp) {
    return (uint32_t)(r * 128 + (((zp >> 2) ^ (r & 7)) << 4) + 4 * (zp & 3));
}
__device__ __forceinline__ void cpasync16(uint32_t dst, const float* src) {
    asm volatile("{ .reg .u64 g; cvta.to.global.u64 g, %1;\n\t"
                 "cp.async.cg.shared.global [%0], [g], 16; }"
                 :: "r"(dst), "l"(src) : "memory");
}
#define CP_COMMIT() asm volatile("cp.async.commit_group;" ::: "memory")
#define CP_WAIT7()  asm volatile("cp.async.wait_group 7;" ::: "memory")

// ======================= prep kernel (grid 15) =======================
__global__ void prep_kernel(const float* __restrict__ W,
                            const float* __restrict__ pmu,
                            const float* __restrict__ pls) {
    const int b = blockIdx.x, tid = threadIdx.x;
    if (b < 14) {
        __shared__ float sc[64 * 57];
        const int c0 = b * 56;
        for (int i = tid; i < 64 * 56; i += 256) {
            const int z = i / 56, c = i - z * 56;
            sc[z * 57 + c] = W[z * XD + c0 + c];
        }
        __syncthreads();
        for (int i = tid; i < 56 * 32; i += 256) {
            const int c = i >> 5, zp = i & 31;
            __nv_bfloat162 bv = __floats2bfloat162_rn(sc[(2 * zp) * 57 + c],
                                                      sc[(2 * zp + 1) * 57 + c]);
            *(uint32_t*)((char*)g_Wt + swz(c0 + c, zp)) = *(uint32_t*)&bv;
        }
    } else {
        const int k = tid >> 2, q = tid & 3;
        float lsum = 0.f, c1 = 0.f;
#pragma unroll
        for (int i = 0; i < 16; i++) {
            const int z = 16 * q + i;
            float ls = pls[k * ZD + z];
            float mu = pmu[k * ZD + z];
            float s2i = expf(-2.f * ls);
            g_s2T[z * KK + k] = s2i;
            g_na2T[z * KK + k] = -2.f * mu * s2i;
            lsum += ls;
            c1 = fmaf(mu * mu, s2i, c1);
        }
#pragma unroll
        for (int o = 1; o < 4; o <<= 1) {
            lsum += __shfl_xor_sync(~0u, lsum, o);
            c1 += __shfl_xor_sync(~0u, c1, o);
        }
        if (q == 0) {
            g_cc2[k] = (float)(-(double)lsum - 32.0 * LOG2PI - 0.5 * (double)c1);
            g_ck2[k] = lsum + 0.5f * c1;
        }
        if (tid == 0) { g_acc = 0ull; g_cnt = 0u; }
    }
}

// ======================= main kernel =======================
extern __shared__ char smem[];

__global__ __launch_bounds__(THREADS, 1)
void main_kernel(const float* __restrict__ x, const float* __restrict__ pi,
                 const float* __restrict__ qmu, const float* __restrict__ qls,
                 const float* __restrict__ eps, const float* __restrict__ bdec,
                 float* __restrict__ out) {
    const int tid = threadIdx.x;
    const int wid = tid >> 5, lane = tid & 31;
    const int rowbase = blockIdx.x * ROWS;
    const uint32_t sbase = smem_u32(smem);
    float* red = (float*)(smem + OFF_RED);
    float* qsumS = (float*)(smem + OFF_QSUM);
    float* biasS = (float*)(smem + OFF_BIAS);
    float* zR = (float*)(smem + OFF_ZR);
    float* v1S = (float*)(smem + OFF_V1);
    float* qmS = (float*)(smem + OFF_QM);
    float* s2T = (float*)(smem + OFF_S2T);
    float* na2T = (float*)(smem + OFF_NA2T);

    // ---- per-warp x-pipeline geometry (GEMM warps only use it) ----
    const int mrow = 16 * (wid & 7);
    const uint32_t xdst = sbase + OFF_XP + (uint32_t)(wid & 7) * 4096 + lane * 16;
    const float* xsrc = x + (size_t)(rowbase + mrow + (lane >> 1)) * XD + 4 * (lane & 1);
#define XISSUE(t) do {                                                         \
    if ((t) < 98) cpasync16(xdst + (((t) & 7) << 9), xsrc + 8 * (t));          \
    CP_COMMIT();                                                               \
} while (0)

    // GEMM warps: prime the x pipeline immediately (overlaps init)
    if (wid < 8) {
#pragma unroll
        for (int t = 0; t < 8; t++) XISSUE(t);
    }

    // ---- init: W tiles 0-39, tables, bias, z/v1/qm/qsum ----
    {
        const uint4* src = (const uint4*)g_Wt;
        uint4* dst = (uint4*)(smem + OFF_WT);
        for (int i = tid; i < 2560; i += THREADS) dst[i] = src[i];
        const uint4* s1 = (const uint4*)g_s2T;
        const uint4* s2 = (const uint4*)g_na2T;
        uint4* d1 = (uint4*)s2T;
        uint4* d2 = (uint4*)na2T;
        for (int i = tid; i < (ZD * KK) / 4; i += THREADS) {
            d1[i] = s1[i];
            d2[i] = s2[i];
        }
    }
    for (int i = tid; i < XD; i += THREADS) biasS[i] = bdec[i];
#pragma unroll
    for (int k = 0; k < 8; k++) {
        const int i = tid + THREADS * k;
        const int r = i >> 5, zp = i & 31;
        const int gi = (rowbase + r) * ZD + 2 * zp;
        float2 qm2 = *(const float2*)(qmu + gi);
        float2 ql2 = *(const float2*)(qls + gi);
        float2 ep2 = *(const float2*)(eps + gi);
        float qs0 = expf(ql2.x), qs1 = expf(ql2.y);
        float z0 = fmaf(qs0, ep2.x, qm2.x);
        float z1 = fmaf(qs1, ep2.y, qm2.y);
        __nv_bfloat162 bv = __floats2bfloat162_rn(z0, z1);
        *(uint32_t*)(smem + OFF_ZBF + swz(r, zp)) = *(uint32_t*)&bv;
        const int rb = r * RSTR + 2 * zp;
        *(float2*)(zR + rb) = make_float2(z0, z1);
        *(float2*)(v1S + rb) = make_float2(fmaf(qs0, qs0, qm2.x * qm2.x),
                                           fmaf(qs1, qs1, qm2.y * qm2.y));
        *(float2*)(qmS + rb) = qm2;
        float qs = ql2.x + ql2.y;
#pragma unroll
        for (int o = 16; o; o >>= 1) qs += __shfl_xor_sync(~0u, qs, o);
        if (lane == 0) qsumS[r] = qs;
    }
    __syncthreads();

    if (wid < 8) {
        // ================= Stage 1: mean GEMM + log_px (warps 0-7) ==========
        float px = 0.f;
        const int g = lane >> 3, lr = lane & 7, gx = g >> 1;
        uint32_t a[16];
        {
            const int ra = mrow + lr + 8 * (g & 1);
            const uint32_t abase = sbase + OFF_ZBF + ra * 128;
#pragma unroll
            for (int kt = 0; kt < 4; kt++)
                ldm_x4(a[4 * kt], a[4 * kt + 1], a[4 * kt + 2], a[4 * kt + 3],
                       abase + (uint32_t)(((gx + 2 * kt) ^ (ra & 7)) << 4));
        }
        const uint32_t bb0 = sbase + OFF_WT + lr * 128 + (uint32_t)((g ^ lr) << 4);
        const uint32_t bb1 = sbase + OFF_WT + lr * 128 + (uint32_t)(((g + 4) ^ lr) << 4);
        const int fcol = 2 * (lane & 3);
        const uint32_t xrd = sbase + OFF_XP + (uint32_t)(wid & 7) * 4096
                             + (uint32_t)((lane >> 2) * 32 + fcol * 4);

#pragma unroll 1
        for (int p = 0; p < 3; p++) {
            const int tlo = 40 * p;
            const int thi = (p == 2) ? 98 : tlo + 40;
            if (p) {
                asm volatile("bar.sync 1, 256;" ::: "memory");
                const int nt4 = (thi - tlo) * 64;   // uint4 count
                const uint4* src = (const uint4*)((const char*)g_Wt + tlo * 1024);
                uint4* dst = (uint4*)(smem + OFF_WT);
                for (int i = tid; i < nt4; i += 256) dst[i] = src[i];
                asm volatile("bar.sync 1, 256;" ::: "memory");
            }
#pragma unroll 2
            for (int t = tlo; t < thi; t++) {
                // B fragments (independent of x arrival)
                uint32_t b[8];
                const uint32_t toff = (uint32_t)(t - tlo) * 1024;
                ldm_x4(b[0], b[1], b[2], b[3], bb0 + toff);
                ldm_x4(b[4], b[5], b[6], b[7], bb1 + toff);
                // x slab for tile t
                CP_WAIT7();
                __syncwarp();
                const uint32_t xs = xrd + (uint32_t)((t & 7) << 9);
                float2 xa = *(const float2*)(smem + (xs - sbase));
                float2 xb = *(const float2*)(smem + (xs - sbase) + 256);
                float2 bb = *(const float2*)(biasS + 8 * t + fcol);
                float cA0 = 0.f, cA1 = 0.f, cA2 = 0.f, cA3 = 0.f;
                float cB0 = 0.f, cB1 = 0.f, cB2 = 0.f, cB3 = 0.f;
                mma_bf16(cA0, cA1, cA2, cA3, a[0], a[1], a[2], a[3], b[0], b[1]);
                mma_bf16(cB0, cB1, cB2, cB3, a[8], a[9], a[10], a[11], b[4], b[5]);
                mma_bf16(cA0, cA1, cA2, cA3, a[4], a[5], a[6], a[7], b[2], b[3]);
                mma_bf16(cB0, cB1, cB2, cB3, a[12], a[13], a[14], a[15], b[6], b[7]);
                float d_;
                d_ = (xa.x - bb.x) - (cA0 + cB0); px = fmaf(d_, d_, px);
                d_ = (xa.y - bb.y) - (cA1 + cB1); px = fmaf(d_, d_, px);
                d_ = (xb.x - bb.x) - (cA2 + cB2); px = fmaf(d_, d_, px);
                d_ = (xb.y - bb.y) - (cA3 + cB3); px = fmaf(d_, d_, px);
                __syncwarp();     // all lanes done reading slab before reuse
                XISSUE(t + 8);
            }
        }
#pragma unroll
        for (int o = 16; o; o >>= 1) px += __shfl_xor_sync(~0u, px, o);
        if (lane == 0) red[wid] = px;
    } else {
        // ============ Stage 2 (warps 8-15): quadratics + in-reg softmax =====
        const int st = tid - 256;
        const int tx = st & 7, ty = st >> 3;
        const int kb = 8 * tx;
        const float* s2p = s2T + kb;
        const float* nap = na2T + kb;
        float cc[8], ck[8];
        *(float4*)cc = *(const float4*)(g_cc2 + kb);
        *(float4*)(cc + 4) = *(const float4*)(g_cc2 + kb + 4);
        *(float4*)ck = *(const float4*)(g_ck2 + kb);
        *(float4*)(ck + 4) = *(const float4*)(g_ck2 + kb + 4);
        float kl_acc = 0.f;

#pragma unroll 1
        for (int pass = 0; pass < 2; pass++) {
            const int r0 = 2 * ty + 64 * pass;
            ull accC[2][4], accK[2][4];
#pragma unroll
            for (int r = 0; r < 2; r++)
#pragma unroll
                for (int k = 0; k < 4; k++) { accC[r][k] = 0ull; accK[r][k] = 0ull; }
            const int rb0 = r0 * RSTR, rb1 = rb0 + RSTR;
#pragma unroll 2
            for (int z = 0; z < ZD; z += 2) {
                ulonglong2 sA0 = *(const ulonglong2*)(s2p + z * KK);
                ulonglong2 sB0 = *(const ulonglong2*)(s2p + z * KK + 4);
                ulonglong2 nA0 = *(const ulonglong2*)(nap + z * KK);
                ulonglong2 nB0 = *(const ulonglong2*)(nap + z * KK + 4);
                ulonglong2 sA1 = *(const ulonglong2*)(s2p + (z + 1) * KK);
                ulonglong2 sB1 = *(const ulonglong2*)(s2p + (z + 1) * KK + 4);
                ulonglong2 nA1 = *(const ulonglong2*)(nap + (z + 1) * KK);
                ulonglong2 nB1 = *(const ulonglong2*)(nap + (z + 1) * KK + 4);
#pragma unroll
                for (int r = 0; r < 2; r++) {
                    const int rb = (r ? rb1 : rb0) + z;
                    float2 zf = *(const float2*)(zR + rb);
                    float2 vf = *(const float2*)(v1S + rb);
                    float2 qf = *(const float2*)(qmS + rb);
                    ull zd = dup2(zf.x), vd = dup2(vf.x), qd = dup2(qf.x);
                    ull t;
                    t = fma2o(sA0.x, zd, nA0.x); accC[r][0] = fma2o(t, zd, accC[r][0]);
                    t = fma2o(sA0.y, zd, nA0.y); accC[r][1] = fma2o(t, zd, accC[r][1]);
                    t = fma2o(sB0.x, zd, nB0.x); accC[r][2] = fma2o(t, zd, accC[r][2]);
                    t = fma2o(sB0.y, zd, nB0.y); accC[r][3] = fma2o(t, zd, accC[r][3]);
                    accK[r][0] = fma2o(sA0.x, vd, accK[r][0]);
                    accK[r][0] = fma2o(nA0.x, qd, accK[r][0]);
                    accK[r][1] = fma2o(sA0.y, vd, accK[r][1]);
                    accK[r][1] = fma2o(nA0.y, qd, accK[r][1]);
                    accK[r][2] = fma2o(sB0.x, vd, accK[r][2]);
                    accK[r][2] = fma2o(nB0.x, qd, accK[r][2]);
                    accK[r][3] = fma2o(sB0.y, vd, accK[r][3]);
                    accK[r][3] = fma2o(nB0.y, qd, accK[r][3]);
                    zd = dup2(zf.y); vd = dup2(vf.y); qd = dup2(qf.y);
                    t = fma2o(sA1.x, zd, nA1.x); accC[r][0] = fma2o(t, zd, accC[r][0]);
                    t = fma2o(sA1.y, zd, nA1.y); accC[r][1] = fma2o(t, zd, accC[r][1]);
                    t = fma2o(sB1.x, zd, nB1.x); accC[r][2] = fma2o(t, zd, accC[r][2]);
                    t = fma2o(sB1.y, zd, nB1.y); accC[r][3] = fma2o(t, zd, accC[r][3]);
                    accK[r][0] = fma2o(sA1.x, vd, accK[r][0]);
                    accK[r][0] = fma2o(nA1.x, qd, accK[r][0]);
                    accK[r][1] = fma2o(sA1.y, vd, accK[r][1]);
                    accK[r][1] = fma2o(nA1.y, qd, accK[r][1]);
                    accK[r][2] = fma2o(sB1.x, vd, accK[r][2]);
                    accK[r][2] = fma2o(nB1.x, qd, accK[r][2]);
                    accK[r][3] = fma2o(sB1.y, vd, accK[r][3]);
                    accK[r][3] = fma2o(nB1.y, qd, accK[r][3]);
                }
            }
#pragma unroll
            for (int r = 0; r < 2; r++) {
                float comp[8], klz[8];
#pragma unroll
                for (int q = 0; q < 4; q++) {
                    float lo, hi;
                    unpack2(accC[r][q], lo, hi);
                    comp[2 * q] = fmaf(-0.5f, lo, cc[2 * q]);
                    comp[2 * q + 1] = fmaf(-0.5f, hi, cc[2 * q + 1]);
                    unpack2(accK[r][q], lo, hi);
                    klz[2 * q] = fmaf(0.5f, lo, ck[2 * q]);
                    klz[2 * q + 1] = fmaf(0.5f, hi, ck[2 * q + 1]);
                }
                const int rl = r0 + r;
                const float* pip = pi + (size_t)(rowbase + rl) * KK + kb;
                float4 pa = *(const float4*)pip;
                float4 pb = *(const float4*)(pip + 4);
                float lp[8];
                lp[0] = __logf(pa.x); lp[1] = __logf(pa.y);
                lp[2] = __logf(pa.z); lp[3] = __logf(pa.w);
                lp[4] = __logf(pb.x); lp[5] = __logf(pb.y);
                lp[6] = __logf(pb.z); lp[7] = __logf(pb.w);
                float p[8], m = -1e30f;
#pragma unroll
                for (int j = 0; j < 8; j++) { p[j] = comp[j] + lp[j]; m = fmaxf(m, p[j]); }
#pragma unroll
                for (int o = 1; o < 8; o <<= 1) m = fmaxf(m, __shfl_xor_sync(~0u, m, o));
                float e[8], es = 0.f;
#pragma unroll
                for (int j = 0; j < 8; j++) { e[j] = __expf(p[j] - m); es += e[j]; }
#pragma unroll
                for (int o = 1; o < 8; o <<= 1) es += __shfl_xor_sync(~0u, es, o);
                const float lse = m + __logf(es);
                const float inv = 1.f / es;
                const float klf = qsumS[rl] + 32.f + lse;
                float ctr = 0.f;
#pragma unroll
                for (int j = 0; j < 8; j++)
                    ctr = fmaf(e[j], (comp[j] - lse) + (klz[j] - klf + lse), ctr);
                ctr *= inv;
#pragma unroll
                for (int o = 1; o < 8; o <<= 1) ctr += __shfl_xor_sync(~0u, ctr, o);
                kl_acc += ctr;
            }
        }
        kl_acc += __shfl_xor_sync(~0u, kl_acc, 8);
        kl_acc += __shfl_xor_sync(~0u, kl_acc, 16);
        if (lane == 0) red[wid] = kl_acc;
    }

    // ---- join + deterministic grid reduction (fixed-point atomics) ----
    __syncthreads();
    if (tid == 0) {
        float sp = 0.f, sk = 0.f;
#pragma unroll
        for (int w = 0; w < 8; w++) { sp += red[w]; sk += red[8 + w]; }
        const double part = -0.5 * (double)sp - (double)sk;
        const long long q = llrint(part * FIXSCALE);
        atomicAdd(&g_acc, (ull)q);
        __threadfence();
        const unsigned t = atomicAdd(&g_cnt, 1u);
        if (t == NBLK - 1) {
            const long long tot = (long long)atomicAdd(&g_acc, 0ull);
            out[0] = (float)((double)tot / FIXSCALE / 16384.0
                             - 0.5 * LOG2PI * (double)XD);
            g_cnt = 0u;
            g_acc = 0ull;
        }
    }
}

extern "C" void kernel_launch(void* const* d_in, const int* in_sizes, int n_in,
                              void* d_out, int out_size) {
    (void)in_sizes; (void)n_in; (void)out_size;
    const float* x    = (const float*)d_in[0];
    const float* pi   = (const float*)d_in[1];
    const float* qmu  = (const float*)d_in[2];
    const float* qls  = (const float*)d_in[3];
    const float* eps  = (const float*)d_in[4];
    const float* pmu  = (const float*)d_in[5];
    const float* pls  = (const float*)d_in[6];
    const float* W    = (const float*)d_in[7];
    const float* bdec = (const float*)d_in[8];

    cudaFuncSetAttribute(main_kernel, cudaFuncAttributeMaxDynamicSharedMemorySize,
                         SMEM_BYTES);
    prep_kernel<<<15, 256>>>(W, pmu, pls);
    main_kernel<<<NBLK, THREADS, SMEM_BYTES>>>(x, pi, qmu, qls, eps, bdec,
                                               (float*)d_out);
}